// round 12
// baseline (speedup 1.0000x reference)
#include <cuda_runtime.h>
#include <cuda_fp16.h>
#include <mma.h>
#include <stdint.h>
using namespace nvcuda;

#define B_  2
#define S_  4096
#define D_  512
#define H_  8
#define DK_ 64

// Scratch (allocation-free rule). All intermediates half.
// Q pre-scaled by 0.125*log2(e): S = QK^T comes out in log2 domain.
__device__ __half   g_Q[(size_t)B_ * H_ * S_ * DK_];
__device__ __half   g_K[(size_t)B_ * H_ * S_ * DK_];
__device__ __half   g_V[(size_t)B_ * H_ * S_ * DK_];
__device__ __half   g_Y[(size_t)B_ * S_ * D_];
__device__ uint32_t g_M[(size_t)B_ * S_ * S_ / 32];   // bit-packed mask

// ---------------------------------------------------------------------------
// PTX helpers
// ---------------------------------------------------------------------------
__device__ __forceinline__ void ldsm4(uint32_t* r, uint32_t addr) {
    asm volatile("ldmatrix.sync.aligned.m8n8.x4.shared.b16 {%0,%1,%2,%3}, [%4];"
                 : "=r"(r[0]), "=r"(r[1]), "=r"(r[2]), "=r"(r[3]) : "r"(addr));
}
__device__ __forceinline__ void ldsm4t(uint32_t* r, uint32_t addr) {
    asm volatile("ldmatrix.sync.aligned.m8n8.x4.trans.shared.b16 {%0,%1,%2,%3}, [%4];"
                 : "=r"(r[0]), "=r"(r[1]), "=r"(r[2]), "=r"(r[3]) : "r"(addr));
}
__device__ __forceinline__ void ldsm2t(uint32_t* r, uint32_t addr) {
    asm volatile("ldmatrix.sync.aligned.m8n8.x2.trans.shared.b16 {%0,%1}, [%2];"
                 : "=r"(r[0]), "=r"(r[1]) : "r"(addr));
}
__device__ __forceinline__ void mma16816(float* c, const uint32_t* a,
                                         uint32_t b0, uint32_t b1) {
    asm volatile(
        "mma.sync.aligned.m16n8k16.row.col.f32.f16.f16.f32 "
        "{%0,%1,%2,%3}, {%4,%5,%6,%7}, {%8,%9}, {%0,%1,%2,%3};"
        : "+f"(c[0]), "+f"(c[1]), "+f"(c[2]), "+f"(c[3])
        : "r"(a[0]), "r"(a[1]), "r"(a[2]), "r"(a[3]), "r"(b0), "r"(b1));
}
__device__ __forceinline__ void cp16(uint32_t dst, const void* src) {
    asm volatile("cp.async.ca.shared.global [%0], [%1], 16;" :: "r"(dst), "l"(src));
}
__device__ __forceinline__ void cp_commit() { asm volatile("cp.async.commit_group;"); }
__device__ __forceinline__ void cp_wait1()  { asm volatile("cp.async.wait_group 1;"); }
__device__ __forceinline__ uint32_t pack_h2(float a, float b) {
    __half2 h = __floats2half2_rn(a, b);
    return *reinterpret_cast<uint32_t*>(&h);
}
__device__ __forceinline__ uint32_t ex2h2(uint32_t x) {   // 2^x on packed f16x2
    uint32_t r;
    asm("ex2.approx.f16x2 %0, %1;" : "=r"(r) : "r"(x));
    return r;
}

// ---------------------------------------------------------------------------
// Projection GEMM, 128x128 CTA tile, FUSED with maskpack on gridDim.z==3.
// z<3: Y = X @ W (pointer select; scale applies to z==0 only).
// HEAD_SPLIT: half out [B,H,S,DK]; else fp32 out [8192,512].
// ---------------------------------------------------------------------------
template <typename TI, bool HEAD_SPLIT, typename TO>
__global__ __launch_bounds__(256) void proj12(
    const TI* __restrict__ X0, const TI* __restrict__ X1, const TI* __restrict__ X2,
    const float* __restrict__ W0, const float* __restrict__ W1, const float* __restrict__ W2,
    TO* __restrict__ Y0, TO* __restrict__ Y1, TO* __restrict__ Y2, float scale0,
    const int* __restrict__ mask, uint32_t* __restrict__ bm)
{
    const int z = blockIdx.z;
    if (z == 3) {   // ---- maskpack: [B,S,S] int32 -> bitmask via warp ballot ----
        const int lane  = threadIdx.x & 31;
        const int cta   = blockIdx.y * 4 + blockIdx.x;           // 0..255
        const int warp  = cta * 8 + (threadIdx.x >> 5);
        const int nwarps = 256 * 8;
        const size_t NW = (size_t)B_ * S_ * S_ / 32;
        for (size_t w = warp; w < NW; w += nwarps) {
            int v = mask[w * 32 + lane];
            uint32_t bits = __ballot_sync(0xffffffffu, v != 0);
            if (lane == 0) bm[w] = bits;
        }
        return;
    }

    __shared__ __half As[128][40];
    __shared__ __half Bs[32][136];
    __shared__ float  stage[8][16][20];

    const TI*    X = (z == 0) ? X0 : (z == 1) ? X1 : X2;
    const float* W = (z == 0) ? W0 : (z == 1) ? W1 : W2;
    TO*          Y = (z == 0) ? Y0 : (z == 1) ? Y1 : Y2;
    const float scale = (z == 0) ? scale0 : 1.0f;

    const int tid  = threadIdx.x;
    const int lane = tid & 31;
    const int warp = tid >> 5;
    const int wm   = warp >> 2;      // 0..1  (64 rows each)
    const int wn   = warp & 3;       // 0..3  (32 cols each)
    const int row0 = blockIdx.y * 128;
    const int n0   = blockIdx.x * 128;

    float4 ar[4];
    uint4  arh[2];
    float4 br[4];

    auto ldg = [&](int k0) {
        if constexpr (sizeof(TI) == 4) {
#pragma unroll
            for (int i = 0; i < 4; i++) {
                int e = i * 256 + tid;
                int r = e >> 3, c = (e & 7) * 4;
                ar[i] = *(const float4*)((const float*)X + (size_t)(row0 + r) * 512 + k0 + c);
            }
        } else {
#pragma unroll
            for (int i = 0; i < 2; i++) {
                int e = i * 256 + tid;
                int r = e >> 2, c = (e & 3) * 8;
                arh[i] = *(const uint4*)((const __half*)X + (size_t)(row0 + r) * 512 + k0 + c);
            }
        }
#pragma unroll
        for (int i = 0; i < 4; i++) {
            int e = i * 256 + tid;
            int r = e >> 5, c = (e & 31) * 4;
            br[i] = *(const float4*)(W + (size_t)(k0 + r) * 512 + n0 + c);
        }
    };
    auto sts = [&]() {
        if constexpr (sizeof(TI) == 4) {
#pragma unroll
            for (int i = 0; i < 4; i++) {
                int e = i * 256 + tid;
                int r = e >> 3, c = (e & 7) * 4;
                As[r][c + 0] = __float2half(ar[i].x);
                As[r][c + 1] = __float2half(ar[i].y);
                As[r][c + 2] = __float2half(ar[i].z);
                As[r][c + 3] = __float2half(ar[i].w);
            }
        } else {
#pragma unroll
            for (int i = 0; i < 2; i++) {
                int e = i * 256 + tid;
                int r = e >> 2, c = (e & 3) * 8;
                *(uint4*)&As[r][c] = arh[i];
            }
        }
#pragma unroll
        for (int i = 0; i < 4; i++) {
            int e = i * 256 + tid;
            int r = e >> 5, c = (e & 31) * 4;
            Bs[r][c + 0] = __float2half(br[i].x);
            Bs[r][c + 1] = __float2half(br[i].y);
            Bs[r][c + 2] = __float2half(br[i].z);
            Bs[r][c + 3] = __float2half(br[i].w);
        }
    };

    wmma::fragment<wmma::accumulator, 16, 16, 16, float> acc[4][2];
#pragma unroll
    for (int i = 0; i < 4; i++)
#pragma unroll
        for (int j = 0; j < 2; j++) wmma::fill_fragment(acc[i][j], 0.0f);

    ldg(0);
    sts();
    __syncthreads();

    for (int kt = 0; kt < 16; kt++) {
        if (kt < 15) ldg(32 * (kt + 1));   // overlap LDG with mma below

#pragma unroll
        for (int kk = 0; kk < 32; kk += 16) {
            wmma::fragment<wmma::matrix_a, 16, 16, 16, __half, wmma::row_major> af[4];
            wmma::fragment<wmma::matrix_b, 16, 16, 16, __half, wmma::row_major> bf[2];
#pragma unroll
            for (int i = 0; i < 4; i++)
                wmma::load_matrix_sync(af[i], &As[wm * 64 + i * 16][kk], 40);
#pragma unroll
            for (int j = 0; j < 2; j++)
                wmma::load_matrix_sync(bf[j], &Bs[kk][wn * 32 + j * 16], 136);
#pragma unroll
            for (int i = 0; i < 4; i++)
#pragma unroll
                for (int j = 0; j < 2; j++)
                    wmma::mma_sync(acc[i][j], af[i], bf[j], acc[i][j]);
        }
        if (kt < 15) {
            __syncthreads();
            sts();
            __syncthreads();
        }
    }

#pragma unroll
    for (int i = 0; i < 4; i++) {
#pragma unroll
        for (int j = 0; j < 2; j++) {
            if constexpr (HEAD_SPLIT) {
                wmma::store_matrix_sync(&stage[warp][0][0], acc[i][j], 20,
                                        wmma::mem_row_major);
                __syncwarp();
                int lr = lane >> 1, lc = (lane & 1) * 8;
                const float* sp = &stage[warp][lr][lc];
                uint32_t u[4];
#pragma unroll
                for (int t = 0; t < 4; t++)
                    u[t] = pack_h2(sp[2 * t] * scale, sp[2 * t + 1] * scale);
                int gr = row0 + wm * 64 + i * 16 + lr;
                int b  = gr >> 12;
                int s  = gr & 4095;
                int gc = n0 + wn * 32 + j * 16 + lc;
                int h  = gc >> 6;
                int dk = gc & 63;
                *(uint4*)((__half*)Y + ((size_t)(b * H_ + h) * S_ + s) * DK_ + dk) =
                    make_uint4(u[0], u[1], u[2], u[3]);
                __syncwarp();
            } else {
                int gr = row0 + wm * 64 + i * 16;
                int gc = n0 + wn * 32 + j * 16;
                wmma::store_matrix_sync((float*)Y + (size_t)gr * 512 + gc, acc[i][j],
                                        512, wmma::mem_row_major);
            }
        }
    }
}

// ---------------------------------------------------------------------------
// Flash attention: 4 warps x 32 q-rows, two 32-col halves per k-tile.
// Log2-domain scores, ex2.approx.f16x2 softmax, bitwise bit-packed mask.
// ONES-COLUMN trick: V smem pad col 64 = 1.0 (written once; cp.async never
// touches pad bytes) -> row sum l accumulates in the tensor pipe as O[:,64].
// 3-stage cp.async ring. 2 CTAs/SM, no register cap.
// smem: Q[128][72]h (18KB) | 3 x { K[64][72]h , V[64][72]h } (54KB) = 72KB
// ---------------------------------------------------------------------------
#define FL_SMEM 73728

__global__ __launch_bounds__(128, 2) void flash12(
    const __half* __restrict__ Qh, const __half* __restrict__ Kh,
    const __half* __restrict__ Vh, const uint32_t* __restrict__ bm,
    __half* __restrict__ Y)
{
    extern __shared__ char sm[];
    const uint32_t smQ  = (uint32_t)__cvta_generic_to_shared(sm);
    const uint32_t smKV = smQ + 18432;            // 3 stages of 18432 B each

    const int tid  = threadIdx.x;
    const int lane = tid & 31;
    const int warp = tid >> 5;       // 0..3
    const int g    = lane >> 2;
    const int qq   = lane & 3;
    const int bh   = blockIdx.x;
    const int b    = bh >> 3;
    const int h    = bh & 7;
    const int q0   = blockIdx.y * 128;
    const int m0   = warp * 32;      // 32 rows per warp

    const __half* Qg = Qh + ((size_t)bh * S_ + q0) * DK_;
    const __half* Kg = Kh + (size_t)bh * S_ * DK_;
    const __half* Vg = Vh + (size_t)bh * S_ * DK_;

    // ---- prologue ----
#pragma unroll
    for (int i = 0; i < 8; i++) {
        int id = tid + 128 * i;
        int r = id >> 3, c = id & 7;
        cp16(smQ + r * 144 + c * 16, Qg + r * 64 + c * 8);
    }
    // V pad columns: col 64 = 1.0, cols 65-71 = 0 (all 3 stages, written once;
    // cp.async only writes bytes 0-127 of each 144B row, pad is stable)
    for (int i = tid; i < 3 * 64; i += 128) {
        int slot = i >> 6, r = i & 63;
        uint4* p = (uint4*)(sm + 18432 + slot * 18432 + 9216 + r * 144 + 128);
        *p = make_uint4(0x00003C00u, 0u, 0u, 0u);   // halves: {1.0, 0 x7}
    }
    auto loadKV = [&](int kt, int slot) {
        uint32_t kb = smKV + slot * 18432;
#pragma unroll
        for (int i = 0; i < 4; i++) {
            int id = tid + 128 * i;
            int r = id >> 3, c = id & 7;
            cp16(kb + r * 144 + c * 16, Kg + (size_t)(kt * 64 + r) * 64 + c * 8);
        }
#pragma unroll
        for (int i = 0; i < 4; i++) {
            int id = tid + 128 * i;
            int r = id >> 3, c = id & 7;
            cp16(kb + 9216 + r * 144 + c * 16, Vg + (size_t)(kt * 64 + r) * 64 + c * 8);
        }
    };
    loadKV(0, 0);
    cp_commit();            // group 0 = Q + KV0
    loadKV(1, 1);
    cp_commit();            // group 1 = KV1

    uint32_t qf[2][4][4];
    float o[2][8][4];
    float ol[2][4];         // ones-column accumulators (l sums)
#pragma unroll
    for (int u = 0; u < 2; u++) {
#pragma unroll
        for (int j = 0; j < 8; j++)
#pragma unroll
            for (int r = 0; r < 4; r++) o[u][j][r] = 0.0f;
#pragma unroll
        for (int r = 0; r < 4; r++) ol[u][r] = 0.0f;
    }

    const uint2* bmp[4];
#pragma unroll
    for (int rr = 0; rr < 4; rr++)
        bmp[rr] = (const uint2*)(bm + ((size_t)b * S_ + q0 + m0 + 8 * rr + g) * 128);

    int slotC = 0, slotP = 2;

#pragma unroll 1
    for (int kt = 0; kt < 64; kt++) {
        cp_wait1();
        __syncthreads();     // group-kt data visible; all warps done with kt-1

        if (kt == 0) {
#pragma unroll
            for (int u = 0; u < 2; u++)
#pragma unroll
                for (int ks = 0; ks < 4; ks++) {
                    uint32_t addr = smQ + (m0 + u * 16 + (lane & 15)) * 144 +
                                    (ks * 16 + (lane >> 4) * 8) * 2;
                    ldsm4(qf[u][ks], addr);
                }
        }
        if (kt + 2 < 64) loadKV(kt + 2, slotP);
        cp_commit();

        const uint32_t kb = smKV + slotC * 18432;
        const uint32_t vb = kb + 9216;

        uint2 mw[4];
#pragma unroll
        for (int rr = 0; rr < 4; rr++) mw[rr] = bmp[rr][kt];

        // ---- two 32-column halves, processed sequentially ----
#pragma unroll
        for (int nh = 0; nh < 2; nh++) {
            // S = Q K^T (log2 domain) for cols [32*nh, 32*nh+32)
            float s[2][4][4];
#pragma unroll
            for (int u = 0; u < 2; u++)
#pragma unroll
                for (int j = 0; j < 4; j++)
#pragma unroll
                    for (int r = 0; r < 4; r++) s[u][j][r] = 0.0f;
#pragma unroll
            for (int j2p = 0; j2p < 2; j2p++) {
                const int j2 = nh * 4 + 2 * j2p;
#pragma unroll
                for (int ks = 0; ks < 4; ks++) {
                    uint32_t kr[4];
                    uint32_t addr = kb +
                        (8 * j2 + (lane & 7) + ((lane >> 4) << 3)) * 144 +
                        (ks * 16 + ((lane >> 3) & 1) * 8) * 2;
                    ldsm4(kr, addr);
                    mma16816(s[0][2 * j2p],     qf[0][ks], kr[0], kr[1]);
                    mma16816(s[0][2 * j2p + 1], qf[0][ks], kr[2], kr[3]);
                    mma16816(s[1][2 * j2p],     qf[1][ks], kr[0], kr[1]);
                    mma16816(s[1][2 * j2p + 1], qf[1][ks], kr[2], kr[3]);
                }
            }

            // p = maskbit ? 2^(s-4) : 0   (f16x2 MUFU, bitwise mask; no fp32 sums)
            uint32_t ph[2][4][2];
#pragma unroll
            for (int u = 0; u < 2; u++) {
                const uint32_t wlo = nh ? mw[2 * u].y     : mw[2 * u].x;
                const uint32_t whi = nh ? mw[2 * u + 1].y : mw[2 * u + 1].x;
#pragma unroll
                for (int j = 0; j < 4; j++) {
                    const int sh = 2 * qq + 8 * j;
                    uint32_t e01 = ex2h2(pack_h2(s[u][j][0] - 4.0f, s[u][j][1] - 4.0f));
                    uint32_t e23 = ex2h2(pack_h2(s[u][j][2] - 4.0f, s[u][j][3] - 4.0f));
                    uint32_t m01 = (((wlo >> sh) & 1u) ? 0x0000FFFFu : 0u) |
                                   (((wlo >> sh) & 2u) ? 0xFFFF0000u : 0u);
                    uint32_t m23 = (((whi >> sh) & 1u) ? 0x0000FFFFu : 0u) |
                                   (((whi >> sh) & 2u) ? 0xFFFF0000u : 0u);
                    ph[u][j][0] = e01 & m01;
                    ph[u][j][1] = e23 & m23;
                }
            }

            // O += P V (+ ones-column -> l) for V rows [32*nh, 32*nh+32)
#pragma unroll
            for (int tl = 0; tl < 2; tl++) {
                const int t = 2 * nh + tl;
#pragma unroll
                for (int j2 = 0; j2 < 8; j2 += 2) {
                    uint32_t vr[4];
                    uint32_t addr = vb +
                        (16 * t + (lane & 7) + ((lane >> 3) & 1) * 8) * 144 +
                        (8 * j2 + (lane >> 4) * 8) * 2;
                    ldsm4t(vr, addr);
#pragma unroll
                    for (int u = 0; u < 2; u++) {
                        uint32_t a[4] = { ph[u][2 * tl][0], ph[u][2 * tl][1],
                                          ph[u][2 * tl + 1][0], ph[u][2 * tl + 1][1] };
                        mma16816(o[u][j2],     a, vr[0], vr[1]);
                        mma16816(o[u][j2 + 1], a, vr[2], vr[3]);
                    }
                }
                // ones column (cols 64-71; only col 64 meaningful)
                uint32_t vo[2];
                ldsm2t(vo, vb + (16 * t + (lane & 15)) * 144 + 128);
#pragma unroll
                for (int u = 0; u < 2; u++) {
                    uint32_t a[4] = { ph[u][2 * tl][0], ph[u][2 * tl][1],
                                      ph[u][2 * tl + 1][0], ph[u][2 * tl + 1][1] };
                    mma16816(ol[u], a, vo[0], vo[1]);
                }
            }
        }

        slotC = (slotC == 2) ? 0 : slotC + 1;
        slotP = (slotP == 2) ? 0 : slotP + 1;
    }

    // ---- epilogue: l lives in qq==0 lanes (col 64 of ones group) ----
#pragma unroll
    for (int u = 0; u < 2; u++) {
        int src = lane & 28;                       // lane with qq==0, same g
        float l0 = __shfl_sync(0xffffffffu, ol[u][0], src);
        float l1 = __shfl_sync(0xffffffffu, ol[u][2], src);
        float il0 = 1.0f / l0;
        float il1 = 1.0f / l1;
        size_t rbase = ((size_t)(b * S_) + q0 + m0 + u * 16 + g) * D_ + h * 64;
#pragma unroll
        for (int j = 0; j < 8; j++) {
            int col = 8 * j + 2 * qq;
            *(uint32_t*)(Y + rbase + col) =
                pack_h2(o[u][j][0] * il0, o[u][j][1] * il0);
            *(uint32_t*)(Y + rbase + 8 * (size_t)D_ + col) =
                pack_h2(o[u][j][2] * il1, o[u][j][3] * il1);
        }
    }
}

// ---------------------------------------------------------------------------
extern "C" void kernel_launch(void* const* d_in, const int* in_sizes, int n_in,
                              void* d_out, int out_size)
{
    const float* q    = (const float*)d_in[0];
    const float* k    = (const float*)d_in[1];
    const float* v    = (const float*)d_in[2];
    const int*   mask = (const int*)d_in[3];
    const float* w_q  = (const float*)d_in[4];
    const float* w_k  = (const float*)d_in[5];
    const float* w_v  = (const float*)d_in[6];
    const float* w_o  = (const float*)d_in[7];
    float* out = (float*)d_out;

    __half *Qh, *Kh, *Vh, *Yb;
    uint32_t* Mb;
    cudaGetSymbolAddress((void**)&Qh, g_Q);
    cudaGetSymbolAddress((void**)&Kh, g_K);
    cudaGetSymbolAddress((void**)&Vh, g_V);
    cudaGetSymbolAddress((void**)&Yb, g_Y);
    cudaGetSymbolAddress((void**)&Mb, g_M);

    static int init = 0;
    if (!init) {
        cudaFuncSetAttribute(flash12, cudaFuncAttributeMaxDynamicSharedMemorySize,
                             FL_SMEM);
        init = 1;
    }

    // fused QKV projections + maskpack (z==3); Q scale folds 1/sqrt(dk)*log2(e)
    dim3 pgrid4(4, 64, 4);
    proj12<float, true, __half><<<pgrid4, 256>>>(q, k, v, w_q, w_k, w_v,
                                                 Qh, Kh, Vh, 0.125f * 1.44269504f,
                                                 mask, Mb);

    dim3 fgrid(16, 32);   // x = b*h, y = q-tile of 128
    flash12<<<fgrid, 128, FL_SMEM>>>(Qh, Kh, Vh, Mb, Yb);

    dim3 pgrid(4, 64, 1);
    proj12<__half, false, float><<<pgrid, 256>>>(Yb, Yb, Yb, w_o, w_o, w_o,
                                                 out, out, out, 1.0f,
                                                 nullptr, nullptr);
}

// round 13
// speedup vs baseline: 1.2342x; 1.2342x over previous
#include <cuda_runtime.h>
#include <cuda_fp16.h>
#include <mma.h>
#include <stdint.h>
using namespace nvcuda;

#define B_  2
#define S_  4096
#define D_  512
#define H_  8
#define DK_ 64

// Scratch (allocation-free rule). All intermediates half.
// Q pre-scaled by 0.125*log2(e): S = QK^T comes out in log2 domain.
__device__ __half   g_Q[(size_t)B_ * H_ * S_ * DK_];
__device__ __half   g_K[(size_t)B_ * H_ * S_ * DK_];
__device__ __half   g_V[(size_t)B_ * H_ * S_ * DK_];
__device__ __half   g_Y[(size_t)B_ * S_ * D_];
__device__ uint32_t g_M[(size_t)B_ * S_ * S_ / 32];   // bit-packed mask

// ---------------------------------------------------------------------------
// PTX helpers
// ---------------------------------------------------------------------------
__device__ __forceinline__ void ldsm4(uint32_t* r, uint32_t addr) {
    asm volatile("ldmatrix.sync.aligned.m8n8.x4.shared.b16 {%0,%1,%2,%3}, [%4];"
                 : "=r"(r[0]), "=r"(r[1]), "=r"(r[2]), "=r"(r[3]) : "r"(addr));
}
__device__ __forceinline__ void ldsm4t(uint32_t* r, uint32_t addr) {
    asm volatile("ldmatrix.sync.aligned.m8n8.x4.trans.shared.b16 {%0,%1,%2,%3}, [%4];"
                 : "=r"(r[0]), "=r"(r[1]), "=r"(r[2]), "=r"(r[3]) : "r"(addr));
}
__device__ __forceinline__ void ldsm2t(uint32_t* r, uint32_t addr) {
    asm volatile("ldmatrix.sync.aligned.m8n8.x2.trans.shared.b16 {%0,%1}, [%2];"
                 : "=r"(r[0]), "=r"(r[1]) : "r"(addr));
}
__device__ __forceinline__ void mma16816(float* c, const uint32_t* a,
                                         uint32_t b0, uint32_t b1) {
    asm volatile(
        "mma.sync.aligned.m16n8k16.row.col.f32.f16.f16.f32 "
        "{%0,%1,%2,%3}, {%4,%5,%6,%7}, {%8,%9}, {%0,%1,%2,%3};"
        : "+f"(c[0]), "+f"(c[1]), "+f"(c[2]), "+f"(c[3])
        : "r"(a[0]), "r"(a[1]), "r"(a[2]), "r"(a[3]), "r"(b0), "r"(b1));
}
__device__ __forceinline__ void cp16(uint32_t dst, const void* src) {
    asm volatile("cp.async.ca.shared.global [%0], [%1], 16;" :: "r"(dst), "l"(src));
}
__device__ __forceinline__ void cp_commit() { asm volatile("cp.async.commit_group;"); }
__device__ __forceinline__ void cp_wait1()  { asm volatile("cp.async.wait_group 1;"); }
__device__ __forceinline__ uint32_t pack_h2(float a, float b) {
    __half2 h = __floats2half2_rn(a, b);
    return *reinterpret_cast<uint32_t*>(&h);
}
__device__ __forceinline__ uint32_t ex2h2(uint32_t x) {   // 2^x on packed f16x2
    uint32_t r;
    asm("ex2.approx.f16x2 %0, %1;" : "=r"(r) : "r"(x));
    return r;
}

// ---------------------------------------------------------------------------
// Mask bit-pack: [B,S,S] int32 -> [B*S*S/32] uint32 via warp ballot.
// Full-width launch (1024 CTAs) -- DRAM-bound, needs the parallelism.
// ---------------------------------------------------------------------------
__global__ __launch_bounds__(256) void maskpack(
    const int* __restrict__ mask, uint32_t* __restrict__ bm)
{
    const int lane   = threadIdx.x & 31;
    const int warp   = (blockIdx.x * blockDim.x + threadIdx.x) >> 5;
    const int nwarps = (gridDim.x * blockDim.x) >> 5;
    const size_t NW  = (size_t)B_ * S_ * S_ / 32;
    for (size_t w = warp; w < NW; w += nwarps) {
        int v = mask[w * 32 + lane];
        uint32_t bits = __ballot_sync(0xffffffffu, v != 0);
        if (lane == 0) bm[w] = bits;
    }
}

// ---------------------------------------------------------------------------
// Projection GEMM, 128x128 CTA tile: Y = X @ W. 8 warps, warp tile 64x32.
// Fused over gridDim.z (X/W/Y pointer select; scale applies to z==0 only).
// HEAD_SPLIT: half out [B,H,S,DK]; else fp32 out [8192,512].
// ---------------------------------------------------------------------------
template <typename TI, bool HEAD_SPLIT, typename TO>
__global__ __launch_bounds__(256) void proj9(
    const TI* __restrict__ X0, const TI* __restrict__ X1, const TI* __restrict__ X2,
    const float* __restrict__ W0, const float* __restrict__ W1, const float* __restrict__ W2,
    TO* __restrict__ Y0, TO* __restrict__ Y1, TO* __restrict__ Y2, float scale0)
{
    __shared__ __half As[128][40];
    __shared__ __half Bs[32][136];
    __shared__ float  stage[8][16][20];

    const int z = blockIdx.z;
    const TI*    X = (z == 0) ? X0 : (z == 1) ? X1 : X2;
    const float* W = (z == 0) ? W0 : (z == 1) ? W1 : W2;
    TO*          Y = (z == 0) ? Y0 : (z == 1) ? Y1 : Y2;
    const float scale = (z == 0) ? scale0 : 1.0f;

    const int tid  = threadIdx.x;
    const int lane = tid & 31;
    const int warp = tid >> 5;
    const int wm   = warp >> 2;      // 0..1  (64 rows each)
    const int wn   = warp & 3;       // 0..3  (32 cols each)
    const int row0 = blockIdx.y * 128;
    const int n0   = blockIdx.x * 128;

    float4 ar[4];
    uint4  arh[2];
    float4 br[4];

    auto ldg = [&](int k0) {
        if constexpr (sizeof(TI) == 4) {
#pragma unroll
            for (int i = 0; i < 4; i++) {
                int e = i * 256 + tid;
                int r = e >> 3, c = (e & 7) * 4;
                ar[i] = *(const float4*)((const float*)X + (size_t)(row0 + r) * 512 + k0 + c);
            }
        } else {
#pragma unroll
            for (int i = 0; i < 2; i++) {
                int e = i * 256 + tid;
                int r = e >> 2, c = (e & 3) * 8;
                arh[i] = *(const uint4*)((const __half*)X + (size_t)(row0 + r) * 512 + k0 + c);
            }
        }
#pragma unroll
        for (int i = 0; i < 4; i++) {
            int e = i * 256 + tid;
            int r = e >> 5, c = (e & 31) * 4;
            br[i] = *(const float4*)(W + (size_t)(k0 + r) * 512 + n0 + c);
        }
    };
    auto sts = [&]() {
        if constexpr (sizeof(TI) == 4) {
#pragma unroll
            for (int i = 0; i < 4; i++) {
                int e = i * 256 + tid;
                int r = e >> 3, c = (e & 7) * 4;
                As[r][c + 0] = __float2half(ar[i].x);
                As[r][c + 1] = __float2half(ar[i].y);
                As[r][c + 2] = __float2half(ar[i].z);
                As[r][c + 3] = __float2half(ar[i].w);
            }
        } else {
#pragma unroll
            for (int i = 0; i < 2; i++) {
                int e = i * 256 + tid;
                int r = e >> 2, c = (e & 3) * 8;
                *(uint4*)&As[r][c] = arh[i];
            }
        }
#pragma unroll
        for (int i = 0; i < 4; i++) {
            int e = i * 256 + tid;
            int r = e >> 5, c = (e & 31) * 4;
            Bs[r][c + 0] = __float2half(br[i].x);
            Bs[r][c + 1] = __float2half(br[i].y);
            Bs[r][c + 2] = __float2half(br[i].z);
            Bs[r][c + 3] = __float2half(br[i].w);
        }
    };

    wmma::fragment<wmma::accumulator, 16, 16, 16, float> acc[4][2];
#pragma unroll
    for (int i = 0; i < 4; i++)
#pragma unroll
        for (int j = 0; j < 2; j++) wmma::fill_fragment(acc[i][j], 0.0f);

    ldg(0);
    sts();
    __syncthreads();

    for (int kt = 0; kt < 16; kt++) {
        if (kt < 15) ldg(32 * (kt + 1));   // overlap LDG with mma below

#pragma unroll
        for (int kk = 0; kk < 32; kk += 16) {
            wmma::fragment<wmma::matrix_a, 16, 16, 16, __half, wmma::row_major> af[4];
            wmma::fragment<wmma::matrix_b, 16, 16, 16, __half, wmma::row_major> bf[2];
#pragma unroll
            for (int i = 0; i < 4; i++)
                wmma::load_matrix_sync(af[i], &As[wm * 64 + i * 16][kk], 40);
#pragma unroll
            for (int j = 0; j < 2; j++)
                wmma::load_matrix_sync(bf[j], &Bs[kk][wn * 32 + j * 16], 136);
#pragma unroll
            for (int i = 0; i < 4; i++)
#pragma unroll
                for (int j = 0; j < 2; j++)
                    wmma::mma_sync(acc[i][j], af[i], bf[j], acc[i][j]);
        }
        if (kt < 15) {
            __syncthreads();
            sts();
            __syncthreads();
        }
    }

#pragma unroll
    for (int i = 0; i < 4; i++) {
#pragma unroll
        for (int j = 0; j < 2; j++) {
            if constexpr (HEAD_SPLIT) {
                wmma::store_matrix_sync(&stage[warp][0][0], acc[i][j], 20,
                                        wmma::mem_row_major);
                __syncwarp();
                int lr = lane >> 1, lc = (lane & 1) * 8;
                const float* sp = &stage[warp][lr][lc];
                uint32_t u[4];
#pragma unroll
                for (int t = 0; t < 4; t++)
                    u[t] = pack_h2(sp[2 * t] * scale, sp[2 * t + 1] * scale);
                int gr = row0 + wm * 64 + i * 16 + lr;
                int b  = gr >> 12;
                int s  = gr & 4095;
                int gc = n0 + wn * 32 + j * 16 + lc;
                int h  = gc >> 6;
                int dk = gc & 63;
                *(uint4*)((__half*)Y + ((size_t)(b * H_ + h) * S_ + s) * DK_ + dk) =
                    make_uint4(u[0], u[1], u[2], u[3]);
                __syncwarp();
            } else {
                int gr = row0 + wm * 64 + i * 16;
                int gc = n0 + wn * 32 + j * 16;
                wmma::store_matrix_sync((float*)Y + (size_t)gr * 512 + gc, acc[i][j],
                                        512, wmma::mem_row_major);
            }
        }
    }
}

// ---------------------------------------------------------------------------
// Flash attention: 4 warps x 32 q-rows, two 32-col halves per k-tile.
// Log2-domain scores, ex2.approx.f16x2 softmax, bitwise bit-packed mask.
// ONES-COLUMN trick: V smem pad col 64 = 1.0 -> row sum l accumulates in the
// tensor pipe as an extra n8 MMA group. 3-stage cp.async ring. 2 CTAs/SM.
// smem: Q[128][72]h (18KB) | 3 x { K[64][72]h , V[64][72]h } (54KB) = 72KB
// ---------------------------------------------------------------------------
#define FL_SMEM 73728

__global__ __launch_bounds__(128, 2) void flash13(
    const __half* __restrict__ Qh, const __half* __restrict__ Kh,
    const __half* __restrict__ Vh, const uint32_t* __restrict__ bm,
    __half* __restrict__ Y)
{
    extern __shared__ char sm[];
    const uint32_t smQ  = (uint32_t)__cvta_generic_to_shared(sm);
    const uint32_t smKV = smQ + 18432;            // 3 stages of 18432 B each

    const int tid  = threadIdx.x;
    const int lane = tid & 31;
    const int warp = tid >> 5;       // 0..3
    const int g    = lane >> 2;
    const int qq   = lane & 3;
    const int bh   = blockIdx.x;
    const int b    = bh >> 3;
    const int h    = bh & 7;
    const int q0   = blockIdx.y * 128;
    const int m0   = warp * 32;      // 32 rows per warp

    const __half* Qg = Qh + ((size_t)bh * S_ + q0) * DK_;
    const __half* Kg = Kh + (size_t)bh * S_ * DK_;
    const __half* Vg = Vh + (size_t)bh * S_ * DK_;

    // ---- prologue ----
#pragma unroll
    for (int i = 0; i < 8; i++) {
        int id = tid + 128 * i;
        int r = id >> 3, c = id & 7;
        cp16(smQ + r * 144 + c * 16, Qg + r * 64 + c * 8);
    }
    // V pad columns: col 64 = 1.0, cols 65-71 = 0 (all 3 stages, written once;
    // cp.async only writes bytes 0-127 of each 144B row, pad is stable)
    for (int i = tid; i < 3 * 64; i += 128) {
        int slot = i >> 6, r = i & 63;
        uint4* p = (uint4*)(sm + 18432 + slot * 18432 + 9216 + r * 144 + 128);
        *p = make_uint4(0x00003C00u, 0u, 0u, 0u);   // halves: {1.0, 0 x7}
    }
    auto loadKV = [&](int kt, int slot) {
        uint32_t kb = smKV + slot * 18432;
#pragma unroll
        for (int i = 0; i < 4; i++) {
            int id = tid + 128 * i;
            int r = id >> 3, c = id & 7;
            cp16(kb + r * 144 + c * 16, Kg + (size_t)(kt * 64 + r) * 64 + c * 8);
        }
#pragma unroll
        for (int i = 0; i < 4; i++) {
            int id = tid + 128 * i;
            int r = id >> 3, c = id & 7;
            cp16(kb + 9216 + r * 144 + c * 16, Vg + (size_t)(kt * 64 + r) * 64 + c * 8);
        }
    };
    loadKV(0, 0);
    cp_commit();            // group 0 = Q + KV0
    loadKV(1, 1);
    cp_commit();            // group 1 = KV1

    uint32_t qf[2][4][4];
    float o[2][8][4];
    float ol[2][4];         // ones-column accumulators (l sums)
#pragma unroll
    for (int u = 0; u < 2; u++) {
#pragma unroll
        for (int j = 0; j < 8; j++)
#pragma unroll
            for (int r = 0; r < 4; r++) o[u][j][r] = 0.0f;
#pragma unroll
        for (int r = 0; r < 4; r++) ol[u][r] = 0.0f;
    }

    const uint2* bmp[4];
#pragma unroll
    for (int rr = 0; rr < 4; rr++)
        bmp[rr] = (const uint2*)(bm + ((size_t)b * S_ + q0 + m0 + 8 * rr + g) * 128);

    int slotC = 0, slotP = 2;

#pragma unroll 1
    for (int kt = 0; kt < 64; kt++) {
        cp_wait1();
        __syncthreads();     // group-kt data visible; all warps done with kt-1

        if (kt == 0) {
#pragma unroll
            for (int u = 0; u < 2; u++)
#pragma unroll
                for (int ks = 0; ks < 4; ks++) {
                    uint32_t addr = smQ + (m0 + u * 16 + (lane & 15)) * 144 +
                                    (ks * 16 + (lane >> 4) * 8) * 2;
                    ldsm4(qf[u][ks], addr);
                }
        }
        if (kt + 2 < 64) loadKV(kt + 2, slotP);
        cp_commit();

        const uint32_t kb = smKV + slotC * 18432;
        const uint32_t vb = kb + 9216;

        uint2 mw[4];
#pragma unroll
        for (int rr = 0; rr < 4; rr++) mw[rr] = bmp[rr][kt];

        // ---- two 32-column halves, processed sequentially ----
#pragma unroll
        for (int nh = 0; nh < 2; nh++) {
            // S = Q K^T (log2 domain) for cols [32*nh, 32*nh+32)
            float s[2][4][4];
#pragma unroll
            for (int u = 0; u < 2; u++)
#pragma unroll
                for (int j = 0; j < 4; j++)
#pragma unroll
                    for (int r = 0; r < 4; r++) s[u][j][r] = 0.0f;
#pragma unroll
            for (int j2p = 0; j2p < 2; j2p++) {
                const int j2 = nh * 4 + 2 * j2p;
#pragma unroll
                for (int ks = 0; ks < 4; ks++) {
                    uint32_t kr[4];
                    uint32_t addr = kb +
                        (8 * j2 + (lane & 7) + ((lane >> 4) << 3)) * 144 +
                        (ks * 16 + ((lane >> 3) & 1) * 8) * 2;
                    ldsm4(kr, addr);
                    mma16816(s[0][2 * j2p],     qf[0][ks], kr[0], kr[1]);
                    mma16816(s[0][2 * j2p + 1], qf[0][ks], kr[2], kr[3]);
                    mma16816(s[1][2 * j2p],     qf[1][ks], kr[0], kr[1]);
                    mma16816(s[1][2 * j2p + 1], qf[1][ks], kr[2], kr[3]);
                }
            }

            // p = maskbit ? 2^(s-4) : 0   (f16x2 MUFU, bitwise mask; no fp32 sums)
            uint32_t ph[2][4][2];
#pragma unroll
            for (int u = 0; u < 2; u++) {
                const uint32_t wlo = nh ? mw[2 * u].y     : mw[2 * u].x;
                const uint32_t whi = nh ? mw[2 * u + 1].y : mw[2 * u + 1].x;
#pragma unroll
                for (int j = 0; j < 4; j++) {
                    const int sh = 2 * qq + 8 * j;
                    uint32_t e01 = ex2h2(pack_h2(s[u][j][0] - 4.0f, s[u][j][1] - 4.0f));
                    uint32_t e23 = ex2h2(pack_h2(s[u][j][2] - 4.0f, s[u][j][3] - 4.0f));
                    uint32_t m01 = (((wlo >> sh) & 1u) ? 0x0000FFFFu : 0u) |
                                   (((wlo >> sh) & 2u) ? 0xFFFF0000u : 0u);
                    uint32_t m23 = (((whi >> sh) & 1u) ? 0x0000FFFFu : 0u) |
                                   (((whi >> sh) & 2u) ? 0xFFFF0000u : 0u);
                    ph[u][j][0] = e01 & m01;
                    ph[u][j][1] = e23 & m23;
                }
            }

            // O += P V (+ ones-column -> l) for V rows [32*nh, 32*nh+32)
#pragma unroll
            for (int tl = 0; tl < 2; tl++) {
                const int t = 2 * nh + tl;
#pragma unroll
                for (int j2 = 0; j2 < 8; j2 += 2) {
                    uint32_t vr[4];
                    uint32_t addr = vb +
                        (16 * t + (lane & 7) + ((lane >> 3) & 1) * 8) * 144 +
                        (8 * j2 + (lane >> 4) * 8) * 2;
                    ldsm4t(vr, addr);
#pragma unroll
                    for (int u = 0; u < 2; u++) {
                        uint32_t a[4] = { ph[u][2 * tl][0], ph[u][2 * tl][1],
                                          ph[u][2 * tl + 1][0], ph[u][2 * tl + 1][1] };
                        mma16816(o[u][j2],     a, vr[0], vr[1]);
                        mma16816(o[u][j2 + 1], a, vr[2], vr[3]);
                    }
                }
                // ones column (cols 64-71; only col 64 meaningful)
                uint32_t vo[2];
                ldsm2t(vo, vb + (16 * t + (lane & 15)) * 144 + 128);
#pragma unroll
                for (int u = 0; u < 2; u++) {
                    uint32_t a[4] = { ph[u][2 * tl][0], ph[u][2 * tl][1],
                                      ph[u][2 * tl + 1][0], ph[u][2 * tl + 1][1] };
                    mma16816(ol[u], a, vo[0], vo[1]);
                }
            }
        }

        slotC = (slotC == 2) ? 0 : slotC + 1;
        slotP = (slotP == 2) ? 0 : slotP + 1;
    }

    // ---- epilogue: l lives in qq==0 lanes (col 64 of ones group) ----
#pragma unroll
    for (int u = 0; u < 2; u++) {
        int src = lane & 28;                       // lane with qq==0, same g
        float l0 = __shfl_sync(0xffffffffu, ol[u][0], src);
        float l1 = __shfl_sync(0xffffffffu, ol[u][2], src);
        float il0 = 1.0f / l0;
        float il1 = 1.0f / l1;
        size_t rbase = ((size_t)(b * S_) + q0 + m0 + u * 16 + g) * D_ + h * 64;
#pragma unroll
        for (int j = 0; j < 8; j++) {
            int col = 8 * j + 2 * qq;
            *(uint32_t*)(Y + rbase + col) =
                pack_h2(o[u][j][0] * il0, o[u][j][1] * il0);
            *(uint32_t*)(Y + rbase + 8 * (size_t)D_ + col) =
                pack_h2(o[u][j][2] * il1, o[u][j][3] * il1);
        }
    }
}

// ---------------------------------------------------------------------------
extern "C" void kernel_launch(void* const* d_in, const int* in_sizes, int n_in,
                              void* d_out, int out_size)
{
    const float* q    = (const float*)d_in[0];
    const float* k    = (const float*)d_in[1];
    const float* v    = (const float*)d_in[2];
    const int*   mask = (const int*)d_in[3];
    const float* w_q  = (const float*)d_in[4];
    const float* w_k  = (const float*)d_in[5];
    const float* w_v  = (const float*)d_in[6];
    const float* w_o  = (const float*)d_in[7];
    float* out = (float*)d_out;

    __half *Qh, *Kh, *Vh, *Yb;
    uint32_t* Mb;
    cudaGetSymbolAddress((void**)&Qh, g_Q);
    cudaGetSymbolAddress((void**)&Kh, g_K);
    cudaGetSymbolAddress((void**)&Vh, g_V);
    cudaGetSymbolAddress((void**)&Yb, g_Y);
    cudaGetSymbolAddress((void**)&Mb, g_M);

    static int init = 0;
    if (!init) {
        cudaFuncSetAttribute(flash13, cudaFuncAttributeMaxDynamicSharedMemorySize,
                             FL_SMEM);
        init = 1;
    }

    maskpack<<<1024, 256>>>(mask, Mb);

    // fused QKV projections; Q scale = (1/sqrt(dk))*log2(e) -> log2-domain scores
    dim3 pgrid3(4, 64, 3);
    proj9<float, true, __half><<<pgrid3, 256>>>(q, k, v, w_q, w_k, w_v,
                                                Qh, Kh, Vh, 0.125f * 1.44269504f);

    dim3 fgrid(16, 32);   // x = b*h, y = q-tile of 128
    flash13<<<fgrid, 128, FL_SMEM>>>(Qh, Kh, Vh, Mb, Yb);

    dim3 pgrid(4, 64, 1);
    proj9<__half, false, float><<<pgrid, 256>>>(Yb, Yb, Yb, w_o, w_o, w_o,
                                                out, out, out, 1.0f);
}

// round 15
// speedup vs baseline: 1.3035x; 1.0561x over previous
#include <cuda_runtime.h>
#include <cuda_fp16.h>
#include <mma.h>
#include <stdint.h>
using namespace nvcuda;

#define B_  2
#define S_  4096
#define D_  512
#define H_  8
#define DK_ 64

// Scratch (allocation-free rule). All intermediates half.
// Q pre-scaled by 0.125*log2(e): S = QK^T comes out in log2 domain.
__device__ __half   g_Q[(size_t)B_ * H_ * S_ * DK_];
__device__ __half   g_K[(size_t)B_ * H_ * S_ * DK_];
__device__ __half   g_V[(size_t)B_ * H_ * S_ * DK_];
__device__ __half   g_Y[(size_t)B_ * S_ * D_];
__device__ uint32_t g_M[(size_t)B_ * S_ * S_ / 32];   // bit-packed mask

// ---------------------------------------------------------------------------
// PTX helpers
// ---------------------------------------------------------------------------
__device__ __forceinline__ void ldsm4(uint32_t* r, uint32_t addr) {
    asm volatile("ldmatrix.sync.aligned.m8n8.x4.shared.b16 {%0,%1,%2,%3}, [%4];"
                 : "=r"(r[0]), "=r"(r[1]), "=r"(r[2]), "=r"(r[3]) : "r"(addr));
}
__device__ __forceinline__ void ldsm4t(uint32_t* r, uint32_t addr) {
    asm volatile("ldmatrix.sync.aligned.m8n8.x4.trans.shared.b16 {%0,%1,%2,%3}, [%4];"
                 : "=r"(r[0]), "=r"(r[1]), "=r"(r[2]), "=r"(r[3]) : "r"(addr));
}
__device__ __forceinline__ void ldsm2t(uint32_t* r, uint32_t addr) {
    asm volatile("ldmatrix.sync.aligned.m8n8.x2.trans.shared.b16 {%0,%1}, [%2];"
                 : "=r"(r[0]), "=r"(r[1]) : "r"(addr));
}
__device__ __forceinline__ void mma16816(float* c, const uint32_t* a,
                                         uint32_t b0, uint32_t b1) {
    asm volatile(
        "mma.sync.aligned.m16n8k16.row.col.f32.f16.f16.f32 "
        "{%0,%1,%2,%3}, {%4,%5,%6,%7}, {%8,%9}, {%0,%1,%2,%3};"
        : "+f"(c[0]), "+f"(c[1]), "+f"(c[2]), "+f"(c[3])
        : "r"(a[0]), "r"(a[1]), "r"(a[2]), "r"(a[3]), "r"(b0), "r"(b1));
}
__device__ __forceinline__ void cp16(uint32_t dst, const void* src) {
    asm volatile("cp.async.ca.shared.global [%0], [%1], 16;" :: "r"(dst), "l"(src));
}
__device__ __forceinline__ void cp_commit() { asm volatile("cp.async.commit_group;"); }
__device__ __forceinline__ void cp_wait1()  { asm volatile("cp.async.wait_group 1;"); }
__device__ __forceinline__ uint32_t pack_h2(float a, float b) {
    __half2 h = __floats2half2_rn(a, b);
    return *reinterpret_cast<uint32_t*>(&h);
}
__device__ __forceinline__ uint32_t ex2h2(uint32_t x) {   // 2^x on packed f16x2
    uint32_t r;
    asm("ex2.approx.f16x2 %0, %1;" : "=r"(r) : "r"(x));
    return r;
}

// ---------------------------------------------------------------------------
// Mask bit-pack: [B,S,S] int32 -> bitmask. int4 per lane (MLP via unroll),
// nibble + 3 OR-shfls per 8-lane group -> 4 output words per warp-iter.
// Bit order preserved: bit i of word w == mask[w*32 + i].
// ---------------------------------------------------------------------------
__global__ __launch_bounds__(256) void maskpack(
    const int* __restrict__ mask, uint32_t* __restrict__ bm)
{
    const int lane   = threadIdx.x & 31;
    const int warp   = (blockIdx.x * blockDim.x + threadIdx.x) >> 5;
    const int nwarps = (gridDim.x * blockDim.x) >> 5;
    const size_t NI  = (size_t)B_ * S_ * S_;
#pragma unroll 4
    for (size_t base = (size_t)warp * 128; base < NI; base += (size_t)nwarps * 128) {
        int4 v = *(const int4*)(mask + base + lane * 4);
        uint32_t nib = (v.x ? 1u : 0u) | (v.y ? 2u : 0u) |
                       (v.z ? 4u : 0u) | (v.w ? 8u : 0u);
        uint32_t bits = nib << ((lane & 7) * 4);
        bits |= __shfl_xor_sync(0xffffffffu, bits, 1);
        bits |= __shfl_xor_sync(0xffffffffu, bits, 2);
        bits |= __shfl_xor_sync(0xffffffffu, bits, 4);
        if ((lane & 7) == 0)
            bm[base / 32 + (lane >> 3)] = bits;
    }
}

// ---------------------------------------------------------------------------
// Projection GEMM, 128x128 CTA tile: Y = X @ W. 8 warps, warp tile 64x32.
// Fused over gridDim.z (X/W/Y pointer select; scale applies to z==0 only).
// HEAD_SPLIT: half out [B,H,S,DK]; else fp32 out [8192,512].
// ---------------------------------------------------------------------------
template <typename TI, bool HEAD_SPLIT, typename TO>
__global__ __launch_bounds__(256) void proj9(
    const TI* __restrict__ X0, const TI* __restrict__ X1, const TI* __restrict__ X2,
    const float* __restrict__ W0, const float* __restrict__ W1, const float* __restrict__ W2,
    TO* __restrict__ Y0, TO* __restrict__ Y1, TO* __restrict__ Y2, float scale0)
{
    __shared__ __half As[128][40];
    __shared__ __half Bs[32][136];
    __shared__ float  stage[8][16][20];

    const int z = blockIdx.z;
    const TI*    X = (z == 0) ? X0 : (z == 1) ? X1 : X2;
    const float* W = (z == 0) ? W0 : (z == 1) ? W1 : W2;
    TO*          Y = (z == 0) ? Y0 : (z == 1) ? Y1 : Y2;
    const float scale = (z == 0) ? scale0 : 1.0f;

    const int tid  = threadIdx.x;
    const int lane = tid & 31;
    const int warp = tid >> 5;
    const int wm   = warp >> 2;      // 0..1  (64 rows each)
    const int wn   = warp & 3;       // 0..3  (32 cols each)
    const int row0 = blockIdx.y * 128;
    const int n0   = blockIdx.x * 128;

    float4 ar[4];
    uint4  arh[2];
    float4 br[4];

    auto ldg = [&](int k0) {
        if constexpr (sizeof(TI) == 4) {
#pragma unroll
            for (int i = 0; i < 4; i++) {
                int e = i * 256 + tid;
                int r = e >> 3, c = (e & 7) * 4;
                ar[i] = *(const float4*)((const float*)X + (size_t)(row0 + r) * 512 + k0 + c);
            }
        } else {
#pragma unroll
            for (int i = 0; i < 2; i++) {
                int e = i * 256 + tid;
                int r = e >> 2, c = (e & 3) * 8;
                arh[i] = *(const uint4*)((const __half*)X + (size_t)(row0 + r) * 512 + k0 + c);
            }
        }
#pragma unroll
        for (int i = 0; i < 4; i++) {
            int e = i * 256 + tid;
            int r = e >> 5, c = (e & 31) * 4;
            br[i] = *(const float4*)(W + (size_t)(k0 + r) * 512 + n0 + c);
        }
    };
    auto sts = [&]() {
        if constexpr (sizeof(TI) == 4) {
#pragma unroll
            for (int i = 0; i < 4; i++) {
                int e = i * 256 + tid;
                int r = e >> 3, c = (e & 7) * 4;
                As[r][c + 0] = __float2half(ar[i].x);
                As[r][c + 1] = __float2half(ar[i].y);
                As[r][c + 2] = __float2half(ar[i].z);
                As[r][c + 3] = __float2half(ar[i].w);
            }
        } else {
#pragma unroll
            for (int i = 0; i < 2; i++) {
                int e = i * 256 + tid;
                int r = e >> 2, c = (e & 3) * 8;
                *(uint4*)&As[r][c] = arh[i];
            }
        }
#pragma unroll
        for (int i = 0; i < 4; i++) {
            int e = i * 256 + tid;
            int r = e >> 5, c = (e & 31) * 4;
            Bs[r][c + 0] = __float2half(br[i].x);
            Bs[r][c + 1] = __float2half(br[i].y);
            Bs[r][c + 2] = __float2half(br[i].z);
            Bs[r][c + 3] = __float2half(br[i].w);
        }
    };

    wmma::fragment<wmma::accumulator, 16, 16, 16, float> acc[4][2];
#pragma unroll
    for (int i = 0; i < 4; i++)
#pragma unroll
        for (int j = 0; j < 2; j++) wmma::fill_fragment(acc[i][j], 0.0f);

    ldg(0);
    sts();
    __syncthreads();

    for (int kt = 0; kt < 16; kt++) {
        if (kt < 15) ldg(32 * (kt + 1));   // overlap LDG with mma below

#pragma unroll
        for (int kk = 0; kk < 32; kk += 16) {
            wmma::fragment<wmma::matrix_a, 16, 16, 16, __half, wmma::row_major> af[4];
            wmma::fragment<wmma::matrix_b, 16, 16, 16, __half, wmma::row_major> bf[2];
#pragma unroll
            for (int i = 0; i < 4; i++)
                wmma::load_matrix_sync(af[i], &As[wm * 64 + i * 16][kk], 40);
#pragma unroll
            for (int j = 0; j < 2; j++)
                wmma::load_matrix_sync(bf[j], &Bs[kk][wn * 32 + j * 16], 136);
#pragma unroll
            for (int i = 0; i < 4; i++)
#pragma unroll
                for (int j = 0; j < 2; j++)
                    wmma::mma_sync(acc[i][j], af[i], bf[j], acc[i][j]);
        }
        if (kt < 15) {
            __syncthreads();
            sts();
            __syncthreads();
        }
    }

#pragma unroll
    for (int i = 0; i < 4; i++) {
#pragma unroll
        for (int j = 0; j < 2; j++) {
            if constexpr (HEAD_SPLIT) {
                wmma::store_matrix_sync(&stage[warp][0][0], acc[i][j], 20,
                                        wmma::mem_row_major);
                __syncwarp();
                int lr = lane >> 1, lc = (lane & 1) * 8;
                const float* sp = &stage[warp][lr][lc];
                uint32_t u[4];
#pragma unroll
                for (int t = 0; t < 4; t++)
                    u[t] = pack_h2(sp[2 * t] * scale, sp[2 * t + 1] * scale);
                int gr = row0 + wm * 64 + i * 16 + lr;
                int b  = gr >> 12;
                int s  = gr & 4095;
                int gc = n0 + wn * 32 + j * 16 + lc;
                int h  = gc >> 6;
                int dk = gc & 63;
                *(uint4*)((__half*)Y + ((size_t)(b * H_ + h) * S_ + s) * DK_ + dk) =
                    make_uint4(u[0], u[1], u[2], u[3]);
                __syncwarp();
            } else {
                int gr = row0 + wm * 64 + i * 16;
                int gc = n0 + wn * 32 + j * 16;
                wmma::store_matrix_sync((float*)Y + (size_t)gr * 512 + gc, acc[i][j],
                                        512, wmma::mem_row_major);
            }
        }
    }
}

// ---------------------------------------------------------------------------
// Flash attention: 4 warps x 32 q-rows, two 32-col halves per k-tile.
// Log2-domain scores (fp32 accumulators), ex2.approx.f16x2 softmax, bitwise
// bit-packed mask. ONES-COLUMN: V pad col 64 = 1.0 -> l accumulates in the
// tensor pipe via an extra n8 MMA. 3-stage cp.async ring. 2 CTAs/SM.
// smem: Q[128][72]h (18KB) | 3 x { K[64][72]h , V[64][72]h } (54KB) = 72KB
// ---------------------------------------------------------------------------
#define FL_SMEM 73728

__global__ __launch_bounds__(128, 2) void flash15(
    const __half* __restrict__ Qh, const __half* __restrict__ Kh,
    const __half* __restrict__ Vh, const uint32_t* __restrict__ bm,
    __half* __restrict__ Y)
{
    extern __shared__ char sm[];
    const uint32_t smQ  = (uint32_t)__cvta_generic_to_shared(sm);
    const uint32_t smKV = smQ + 18432;            // 3 stages of 18432 B each

    const int tid  = threadIdx.x;
    const int lane = tid & 31;
    const int warp = tid >> 5;       // 0..3
    const int g    = lane >> 2;
    const int qq   = lane & 3;
    const int bh   = blockIdx.x;
    const int b    = bh >> 3;
    const int h    = bh & 7;
    const int q0   = blockIdx.y * 128;
    const int m0   = warp * 32;      // 32 rows per warp

    const __half* Qg = Qh + ((size_t)bh * S_ + q0) * DK_;
    const __half* Kg = Kh + (size_t)bh * S_ * DK_;
    const __half* Vg = Vh + (size_t)bh * S_ * DK_;

    // ---- prologue ----
#pragma unroll
    for (int i = 0; i < 8; i++) {
        int id = tid + 128 * i;
        int r = id >> 3, c = id & 7;
        cp16(smQ + r * 144 + c * 16, Qg + r * 64 + c * 8);
    }
    // V pad columns: col 64 = 1.0, cols 65-71 = 0 (all 3 stages, written once;
    // cp.async only writes bytes 0-127 of each 144B row, pad is stable)
    for (int i = tid; i < 3 * 64; i += 128) {
        int slot = i >> 6, r = i & 63;
        uint4* p = (uint4*)(sm + 18432 + slot * 18432 + 9216 + r * 144 + 128);
        *p = make_uint4(0x00003C00u, 0u, 0u, 0u);   // halves: {1.0, 0 x7}
    }
    auto loadKV = [&](int kt, int slot) {
        uint32_t kb = smKV + slot * 18432;
#pragma unroll
        for (int i = 0; i < 4; i++) {
            int id = tid + 128 * i;
            int r = id >> 3, c = id & 7;
            cp16(kb + r * 144 + c * 16, Kg + (size_t)(kt * 64 + r) * 64 + c * 8);
        }
#pragma unroll
        for (int i = 0; i < 4; i++) {
            int id = tid + 128 * i;
            int r = id >> 3, c = id & 7;
            cp16(kb + 9216 + r * 144 + c * 16, Vg + (size_t)(kt * 64 + r) * 64 + c * 8);
        }
    };
    loadKV(0, 0);
    cp_commit();            // group 0 = Q + KV0
    loadKV(1, 1);
    cp_commit();            // group 1 = KV1

    uint32_t qf[2][4][4];
    float o[2][8][4];
    float ol[2][4];         // ones-column accumulators (l sums)
#pragma unroll
    for (int u = 0; u < 2; u++) {
#pragma unroll
        for (int j = 0; j < 8; j++)
#pragma unroll
            for (int r = 0; r < 4; r++) o[u][j][r] = 0.0f;
#pragma unroll
        for (int r = 0; r < 4; r++) ol[u][r] = 0.0f;
    }

    const uint2* bmp[4];
#pragma unroll
    for (int rr = 0; rr < 4; rr++)
        bmp[rr] = (const uint2*)(bm + ((size_t)b * S_ + q0 + m0 + 8 * rr + g) * 128);

    int slotC = 0, slotP = 2;

#pragma unroll 1
    for (int kt = 0; kt < 64; kt++) {
        cp_wait1();
        __syncthreads();     // group-kt data visible; all warps done with kt-1

        if (kt == 0) {
#pragma unroll
            for (int u = 0; u < 2; u++)
#pragma unroll
                for (int ks = 0; ks < 4; ks++) {
                    uint32_t addr = smQ + (m0 + u * 16 + (lane & 15)) * 144 +
                                    (ks * 16 + (lane >> 4) * 8) * 2;
                    ldsm4(qf[u][ks], addr);
                }
        }
        if (kt + 2 < 64) loadKV(kt + 2, slotP);
        cp_commit();

        const uint32_t kb = smKV + slotC * 18432;
        const uint32_t vb = kb + 9216;

        uint2 mw[4];
#pragma unroll
        for (int rr = 0; rr < 4; rr++) mw[rr] = bmp[rr][kt];

        // ---- two 32-column halves, processed sequentially ----
#pragma unroll
        for (int nh = 0; nh < 2; nh++) {
            // S = Q K^T (log2 domain, fp32 accumulators) for cols [32*nh,+32)
            float s[2][4][4];
#pragma unroll
            for (int u = 0; u < 2; u++)
#pragma unroll
                for (int j = 0; j < 4; j++)
#pragma unroll
                    for (int r = 0; r < 4; r++) s[u][j][r] = 0.0f;
#pragma unroll
            for (int j2p = 0; j2p < 2; j2p++) {
                const int j2 = nh * 4 + 2 * j2p;
#pragma unroll
                for (int ks = 0; ks < 4; ks++) {
                    uint32_t kr[4];
                    uint32_t addr = kb +
                        (8 * j2 + (lane & 7) + ((lane >> 4) << 3)) * 144 +
                        (ks * 16 + ((lane >> 3) & 1) * 8) * 2;
                    ldsm4(kr, addr);
                    mma16816(s[0][2 * j2p],     qf[0][ks], kr[0], kr[1]);
                    mma16816(s[0][2 * j2p + 1], qf[0][ks], kr[2], kr[3]);
                    mma16816(s[1][2 * j2p],     qf[1][ks], kr[0], kr[1]);
                    mma16816(s[1][2 * j2p + 1], qf[1][ks], kr[2], kr[3]);
                }
            }

            // p = maskbit ? 2^(s-4) : 0   (f16x2 MUFU, bitwise mask)
            uint32_t ph[2][4][2];
#pragma unroll
            for (int u = 0; u < 2; u++) {
                const uint32_t wlo = nh ? mw[2 * u].y     : mw[2 * u].x;
                const uint32_t whi = nh ? mw[2 * u + 1].y : mw[2 * u + 1].x;
#pragma unroll
                for (int j = 0; j < 4; j++) {
                    const int sh = 2 * qq + 8 * j;
                    uint32_t e01 = ex2h2(pack_h2(s[u][j][0] - 4.0f, s[u][j][1] - 4.0f));
                    uint32_t e23 = ex2h2(pack_h2(s[u][j][2] - 4.0f, s[u][j][3] - 4.0f));
                    uint32_t m01 = (((wlo >> sh) & 1u) ? 0x0000FFFFu : 0u) |
                                   (((wlo >> sh) & 2u) ? 0xFFFF0000u : 0u);
                    uint32_t m23 = (((whi >> sh) & 1u) ? 0x0000FFFFu : 0u) |
                                   (((whi >> sh) & 2u) ? 0xFFFF0000u : 0u);
                    ph[u][j][0] = e01 & m01;
                    ph[u][j][1] = e23 & m23;
                }
            }

            // O += P V (+ ones-column -> l) for V rows [32*nh, 32*nh+32)
#pragma unroll
            for (int tl = 0; tl < 2; tl++) {
                const int t = 2 * nh + tl;
#pragma unroll
                for (int j2 = 0; j2 < 8; j2 += 2) {
                    uint32_t vr[4];
                    uint32_t addr = vb +
                        (16 * t + (lane & 7) + ((lane >> 3) & 1) * 8) * 144 +
                        (8 * j2 + (lane >> 4) * 8) * 2;
                    ldsm4t(vr, addr);
#pragma unroll
                    for (int u = 0; u < 2; u++) {
                        uint32_t a[4] = { ph[u][2 * tl][0], ph[u][2 * tl][1],
                                          ph[u][2 * tl + 1][0], ph[u][2 * tl + 1][1] };
                        mma16816(o[u][j2],     a, vr[0], vr[1]);
                        mma16816(o[u][j2 + 1], a, vr[2], vr[3]);
                    }
                }
                // ones column (cols 64-71; only col 64 meaningful)
                uint32_t vo[2];
                ldsm2t(vo, vb + (16 * t + (lane & 15)) * 144 + 128);
#pragma unroll
                for (int u = 0; u < 2; u++) {
                    uint32_t a[4] = { ph[u][2 * tl][0], ph[u][2 * tl][1],
                                      ph[u][2 * tl + 1][0], ph[u][2 * tl + 1][1] };
                    mma16816(ol[u], a, vo[0], vo[1]);
                }
            }
        }

        slotC = (slotC == 2) ? 0 : slotC + 1;
        slotP = (slotP == 2) ? 0 : slotP + 1;
    }

    // ---- epilogue: l lives in qq==0 lanes (col 64 of ones group) ----
#pragma unroll
    for (int u = 0; u < 2; u++) {
        int src = lane & 28;                       // lane with qq==0, same g
        float l0 = __shfl_sync(0xffffffffu, ol[u][0], src);
        float l1 = __shfl_sync(0xffffffffu, ol[u][2], src);
        float il0 = 1.0f / l0;
        float il1 = 1.0f / l1;
        size_t rbase = ((size_t)(b * S_) + q0 + m0 + u * 16 + g) * D_ + h * 64;
#pragma unroll
        for (int j = 0; j < 8; j++) {
            int col = 8 * j + 2 * qq;
            *(uint32_t*)(Y + rbase + col) =
                pack_h2(o[u][j][0] * il0, o[u][j][1] * il0);
            *(uint32_t*)(Y + rbase + 8 * (size_t)D_ + col) =
                pack_h2(o[u][j][2] * il1, o[u][j][3] * il1);
        }
    }
}

// ---------------------------------------------------------------------------
extern "C" void kernel_launch(void* const* d_in, const int* in_sizes, int n_in,
                              void* d_out, int out_size)
{
    const float* q    = (const float*)d_in[0];
    const float* k    = (const float*)d_in[1];
    const float* v    = (const float*)d_in[2];
    const int*   mask = (const int*)d_in[3];
    const float* w_q  = (const float*)d_in[4];
    const float* w_k  = (const float*)d_in[5];
    const float* w_v  = (const float*)d_in[6];
    const float* w_o  = (const float*)d_in[7];
    float* out = (float*)d_out;

    __half *Qh, *Kh, *Vh, *Yb;
    uint32_t* Mb;
    cudaGetSymbolAddress((void**)&Qh, g_Q);
    cudaGetSymbolAddress((void**)&Kh, g_K);
    cudaGetSymbolAddress((void**)&Vh, g_V);
    cudaGetSymbolAddress((void**)&Yb, g_Y);
    cudaGetSymbolAddress((void**)&Mb, g_M);

    static int init = 0;
    if (!init) {
        cudaFuncSetAttribute(flash15, cudaFuncAttributeMaxDynamicSharedMemorySize,
                             FL_SMEM);
        init = 1;
    }

    maskpack<<<1024, 256>>>(mask, Mb);

    // fused QKV projections; Q scale = (1/sqrt(dk))*log2(e) -> log2-domain scores
    dim3 pgrid3(4, 64, 3);
    proj9<float, true, __half><<<pgrid3, 256>>>(q, k, v, w_q, w_k, w_v,
                                                Qh, Kh, Vh, 0.125f * 1.44269504f);

    dim3 fgrid(16, 32);   // x = b*h, y = q-tile of 128
    flash15<<<fgrid, 128, FL_SMEM>>>(Qh, Kh, Vh, Mb, Yb);

    dim3 pgrid(4, 64, 1);
    proj9<__half, false, float><<<pgrid, 256>>>(Yb, Yb, Yb, w_o, w_o, w_o,
                                                out, out, out, 1.0f);
}

// round 16
// speedup vs baseline: 1.3590x; 1.0426x over previous
#include <cuda_runtime.h>
#include <cuda_fp16.h>
#include <mma.h>
#include <stdint.h>
using namespace nvcuda;

#define B_  2
#define S_  4096
#define D_  512
#define H_  8
#define DK_ 64

// Scratch (allocation-free rule). All intermediates half.
// Q pre-scaled by 0.125*log2(e): S = QK^T comes out in log2 domain.
__device__ __half   g_Q[(size_t)B_ * H_ * S_ * DK_];
__device__ __half   g_K[(size_t)B_ * H_ * S_ * DK_];
__device__ __half   g_V[(size_t)B_ * H_ * S_ * DK_];
__device__ __half   g_Y[(size_t)B_ * S_ * D_];
__device__ uint32_t g_M[(size_t)B_ * S_ * S_ / 32];   // bit-packed mask

// ---------------------------------------------------------------------------
// PTX helpers
// ---------------------------------------------------------------------------
__device__ __forceinline__ void ldsm4(uint32_t* r, uint32_t addr) {
    asm volatile("ldmatrix.sync.aligned.m8n8.x4.shared.b16 {%0,%1,%2,%3}, [%4];"
                 : "=r"(r[0]), "=r"(r[1]), "=r"(r[2]), "=r"(r[3]) : "r"(addr));
}
__device__ __forceinline__ void ldsm4t(uint32_t* r, uint32_t addr) {
    asm volatile("ldmatrix.sync.aligned.m8n8.x4.trans.shared.b16 {%0,%1,%2,%3}, [%4];"
                 : "=r"(r[0]), "=r"(r[1]), "=r"(r[2]), "=r"(r[3]) : "r"(addr));
}
__device__ __forceinline__ void ldsm2t(uint32_t* r, uint32_t addr) {
    asm volatile("ldmatrix.sync.aligned.m8n8.x2.trans.shared.b16 {%0,%1}, [%2];"
                 : "=r"(r[0]), "=r"(r[1]) : "r"(addr));
}
__device__ __forceinline__ void mma16816(float* c, const uint32_t* a,
                                         uint32_t b0, uint32_t b1) {
    asm volatile(
        "mma.sync.aligned.m16n8k16.row.col.f32.f16.f16.f32 "
        "{%0,%1,%2,%3}, {%4,%5,%6,%7}, {%8,%9}, {%0,%1,%2,%3};"
        : "+f"(c[0]), "+f"(c[1]), "+f"(c[2]), "+f"(c[3])
        : "r"(a[0]), "r"(a[1]), "r"(a[2]), "r"(a[3]), "r"(b0), "r"(b1));
}
__device__ __forceinline__ void cp16(uint32_t dst, const void* src) {
    asm volatile("cp.async.ca.shared.global [%0], [%1], 16;" :: "r"(dst), "l"(src));
}
__device__ __forceinline__ void cp_commit() { asm volatile("cp.async.commit_group;"); }
__device__ __forceinline__ void cp_wait1()  { asm volatile("cp.async.wait_group 1;"); }
__device__ __forceinline__ uint32_t pack_h2(float a, float b) {
    __half2 h = __floats2half2_rn(a, b);
    return *reinterpret_cast<uint32_t*>(&h);
}
__device__ __forceinline__ uint32_t ex2h2(uint32_t x) {   // 2^x on packed f16x2
    uint32_t r;
    asm("ex2.approx.f16x2 %0, %1;" : "=r"(r) : "r"(x));
    return r;
}

// ---------------------------------------------------------------------------
// Mask bit-pack: [B,S,S] int32 -> bitmask. int4 per lane (MLP via unroll),
// nibble + 3 OR-shfls per 8-lane group -> 4 output words per warp-iter.
// ---------------------------------------------------------------------------
__global__ __launch_bounds__(256) void maskpack(
    const int* __restrict__ mask, uint32_t* __restrict__ bm)
{
    const int lane   = threadIdx.x & 31;
    const int warp   = (blockIdx.x * blockDim.x + threadIdx.x) >> 5;
    const int nwarps = (gridDim.x * blockDim.x) >> 5;
    const size_t NI  = (size_t)B_ * S_ * S_;
#pragma unroll 4
    for (size_t base = (size_t)warp * 128; base < NI; base += (size_t)nwarps * 128) {
        int4 v = *(const int4*)(mask + base + lane * 4);
        uint32_t nib = (v.x ? 1u : 0u) | (v.y ? 2u : 0u) |
                       (v.z ? 4u : 0u) | (v.w ? 8u : 0u);
        uint32_t bits = nib << ((lane & 7) * 4);
        bits |= __shfl_xor_sync(0xffffffffu, bits, 1);
        bits |= __shfl_xor_sync(0xffffffffu, bits, 2);
        bits |= __shfl_xor_sync(0xffffffffu, bits, 4);
        if ((lane & 7) == 0)
            bm[base / 32 + (lane >> 3)] = bits;
    }
}

// ---------------------------------------------------------------------------
// Projection GEMM, 128x128 CTA tile: Y = X @ W. 8 warps, warp tile 64x32.
// Fused over gridDim.z (X/W/Y pointer select; scale applies to z==0 only).
// HEAD_SPLIT: half out [B,H,S,DK]; else fp32 out [8192,512].
// ---------------------------------------------------------------------------
template <typename TI, bool HEAD_SPLIT, typename TO>
__global__ __launch_bounds__(256) void proj9(
    const TI* __restrict__ X0, const TI* __restrict__ X1, const TI* __restrict__ X2,
    const float* __restrict__ W0, const float* __restrict__ W1, const float* __restrict__ W2,
    TO* __restrict__ Y0, TO* __restrict__ Y1, TO* __restrict__ Y2, float scale0)
{
    __shared__ __half As[128][40];
    __shared__ __half Bs[32][136];
    __shared__ float  stage[8][16][20];

    const int z = blockIdx.z;
    const TI*    X = (z == 0) ? X0 : (z == 1) ? X1 : X2;
    const float* W = (z == 0) ? W0 : (z == 1) ? W1 : W2;
    TO*          Y = (z == 0) ? Y0 : (z == 1) ? Y1 : Y2;
    const float scale = (z == 0) ? scale0 : 1.0f;

    const int tid  = threadIdx.x;
    const int lane = tid & 31;
    const int warp = tid >> 5;
    const int wm   = warp >> 2;
    const int wn   = warp & 3;
    const int row0 = blockIdx.y * 128;
    const int n0   = blockIdx.x * 128;

    float4 ar[4];
    uint4  arh[2];
    float4 br[4];

    auto ldg = [&](int k0) {
        if constexpr (sizeof(TI) == 4) {
#pragma unroll
            for (int i = 0; i < 4; i++) {
                int e = i * 256 + tid;
                int r = e >> 3, c = (e & 7) * 4;
                ar[i] = *(const float4*)((const float*)X + (size_t)(row0 + r) * 512 + k0 + c);
            }
        } else {
#pragma unroll
            for (int i = 0; i < 2; i++) {
                int e = i * 256 + tid;
                int r = e >> 2, c = (e & 3) * 8;
                arh[i] = *(const uint4*)((const __half*)X + (size_t)(row0 + r) * 512 + k0 + c);
            }
        }
#pragma unroll
        for (int i = 0; i < 4; i++) {
            int e = i * 256 + tid;
            int r = e >> 5, c = (e & 31) * 4;
            br[i] = *(const float4*)(W + (size_t)(k0 + r) * 512 + n0 + c);
        }
    };
    auto sts = [&]() {
        if constexpr (sizeof(TI) == 4) {
#pragma unroll
            for (int i = 0; i < 4; i++) {
                int e = i * 256 + tid;
                int r = e >> 3, c = (e & 7) * 4;
                As[r][c + 0] = __float2half(ar[i].x);
                As[r][c + 1] = __float2half(ar[i].y);
                As[r][c + 2] = __float2half(ar[i].z);
                As[r][c + 3] = __float2half(ar[i].w);
            }
        } else {
#pragma unroll
            for (int i = 0; i < 2; i++) {
                int e = i * 256 + tid;
                int r = e >> 2, c = (e & 3) * 8;
                *(uint4*)&As[r][c] = arh[i];
            }
        }
#pragma unroll
        for (int i = 0; i < 4; i++) {
            int e = i * 256 + tid;
            int r = e >> 5, c = (e & 31) * 4;
            Bs[r][c + 0] = __float2half(br[i].x);
            Bs[r][c + 1] = __float2half(br[i].y);
            Bs[r][c + 2] = __float2half(br[i].z);
            Bs[r][c + 3] = __float2half(br[i].w);
        }
    };

    wmma::fragment<wmma::accumulator, 16, 16, 16, float> acc[4][2];
#pragma unroll
    for (int i = 0; i < 4; i++)
#pragma unroll
        for (int j = 0; j < 2; j++) wmma::fill_fragment(acc[i][j], 0.0f);

    ldg(0);
    sts();
    __syncthreads();

    for (int kt = 0; kt < 16; kt++) {
        if (kt < 15) ldg(32 * (kt + 1));

#pragma unroll
        for (int kk = 0; kk < 32; kk += 16) {
            wmma::fragment<wmma::matrix_a, 16, 16, 16, __half, wmma::row_major> af[4];
            wmma::fragment<wmma::matrix_b, 16, 16, 16, __half, wmma::row_major> bf[2];
#pragma unroll
            for (int i = 0; i < 4; i++)
                wmma::load_matrix_sync(af[i], &As[wm * 64 + i * 16][kk], 40);
#pragma unroll
            for (int j = 0; j < 2; j++)
                wmma::load_matrix_sync(bf[j], &Bs[kk][wn * 32 + j * 16], 136);
#pragma unroll
            for (int i = 0; i < 4; i++)
#pragma unroll
                for (int j = 0; j < 2; j++)
                    wmma::mma_sync(acc[i][j], af[i], bf[j], acc[i][j]);
        }
        if (kt < 15) {
            __syncthreads();
            sts();
            __syncthreads();
        }
    }

#pragma unroll
    for (int i = 0; i < 4; i++) {
#pragma unroll
        for (int j = 0; j < 2; j++) {
            if constexpr (HEAD_SPLIT) {
                wmma::store_matrix_sync(&stage[warp][0][0], acc[i][j], 20,
                                        wmma::mem_row_major);
                __syncwarp();
                int lr = lane >> 1, lc = (lane & 1) * 8;
                const float* sp = &stage[warp][lr][lc];
                uint32_t u[4];
#pragma unroll
                for (int t = 0; t < 4; t++)
                    u[t] = pack_h2(sp[2 * t] * scale, sp[2 * t + 1] * scale);
                int gr = row0 + wm * 64 + i * 16 + lr;
                int b  = gr >> 12;
                int s  = gr & 4095;
                int gc = n0 + wn * 32 + j * 16 + lc;
                int h  = gc >> 6;
                int dk = gc & 63;
                *(uint4*)((__half*)Y + ((size_t)(b * H_ + h) * S_ + s) * DK_ + dk) =
                    make_uint4(u[0], u[1], u[2], u[3]);
                __syncwarp();
            } else {
                int gr = row0 + wm * 64 + i * 16;
                int gc = n0 + wn * 32 + j * 16;
                wmma::store_matrix_sync((float*)Y + (size_t)gr * 512 + gc, acc[i][j],
                                        512, wmma::mem_row_major);
            }
        }
    }
}

// ---------------------------------------------------------------------------
// Flash attention: 4 warps x 32 q-rows, BK=128 k-tiles processed in FOUR
// 32-col slices (small live ranges, no spill). 32 loop iterations (halved
// overhead). Log2-domain scores, NO bias (safe: p <= ~90 in f16), bitwise
// bit-packed mask (uint4 per row per tile). ONES-COLUMN l. 2-stage ring.
// smem: Q[128][144]B (18KB) | 2 x { K[128][144] , V[128][144] } (72KB) = 90KB
// ---------------------------------------------------------------------------
#define FL_SMEM 92160

__global__ __launch_bounds__(128, 2) void flash16(
    const __half* __restrict__ Qh, const __half* __restrict__ Kh,
    const __half* __restrict__ Vh, const uint32_t* __restrict__ bm,
    __half* __restrict__ Y)
{
    extern __shared__ char sm[];
    const uint32_t smQ  = (uint32_t)__cvta_generic_to_shared(sm);
    const uint32_t smKV = smQ + 18432;            // 2 stages of 36864 B each

    const int tid  = threadIdx.x;
    const int lane = tid & 31;
    const int warp = tid >> 5;       // 0..3
    const int g    = lane >> 2;
    const int qq   = lane & 3;
    const int bh   = blockIdx.x;
    const int b    = bh >> 3;
    const int h    = bh & 7;
    const int q0   = blockIdx.y * 128;
    const int m0   = warp * 32;      // 32 rows per warp

    const __half* Qg = Qh + ((size_t)bh * S_ + q0) * DK_;
    const __half* Kg = Kh + (size_t)bh * S_ * DK_;
    const __half* Vg = Vh + (size_t)bh * S_ * DK_;

    // ---- prologue ----
#pragma unroll
    for (int i = 0; i < 8; i++) {
        int id = tid + 128 * i;
        int r = id >> 3, c = id & 7;
        cp16(smQ + r * 144 + c * 16, Qg + r * 64 + c * 8);
    }
    // V pad columns: col 64 = 1.0, cols 65-71 = 0 (both stages, written once;
    // cp.async only writes bytes 0-127 of each 144B row, pad is stable)
    for (int i = tid; i < 2 * 128; i += 128) {
        int slot = i >> 7, r = i & 127;
        uint4* p = (uint4*)(sm + 18432 + slot * 36864 + 18432 + r * 144 + 128);
        *p = make_uint4(0x00003C00u, 0u, 0u, 0u);   // halves: {1.0, 0 x7}
    }
    auto loadKV = [&](int kt, int slot) {   // kt = 128-wide tile index
        uint32_t kb = smKV + slot * 36864;
#pragma unroll
        for (int i = 0; i < 8; i++) {
            int id = tid + 128 * i;
            int r = id >> 3, c = id & 7;
            cp16(kb + r * 144 + c * 16, Kg + (size_t)(kt * 128 + r) * 64 + c * 8);
        }
#pragma unroll
        for (int i = 0; i < 8; i++) {
            int id = tid + 128 * i;
            int r = id >> 3, c = id & 7;
            cp16(kb + 18432 + r * 144 + c * 16, Vg + (size_t)(kt * 128 + r) * 64 + c * 8);
        }
    };
    loadKV(0, 0);
    cp_commit();            // group 0 = Q + KV0
    loadKV(1, 1);
    cp_commit();            // group 1 = KV1

    uint32_t qf[2][4][4];
    float o[2][8][4];
    float ol[2][4];         // ones-column accumulators (l sums)
#pragma unroll
    for (int u = 0; u < 2; u++) {
#pragma unroll
        for (int j = 0; j < 8; j++)
#pragma unroll
            for (int r = 0; r < 4; r++) o[u][j][r] = 0.0f;
#pragma unroll
        for (int r = 0; r < 4; r++) ol[u][r] = 0.0f;
    }

    const uint4* bmp[4];
#pragma unroll
    for (int rr = 0; rr < 4; rr++)
        bmp[rr] = (const uint4*)(bm + ((size_t)b * S_ + q0 + m0 + 8 * rr + g) * 128);

#pragma unroll 1
    for (int kt = 0; kt < 32; kt++) {
        cp_wait1();
        __syncthreads();     // group-kt data visible to all warps

        if (kt == 0) {
#pragma unroll
            for (int u = 0; u < 2; u++)
#pragma unroll
                for (int ks = 0; ks < 4; ks++) {
                    uint32_t addr = smQ + (m0 + u * 16 + (lane & 15)) * 144 +
                                    (ks * 16 + (lane >> 4) * 8) * 2;
                    ldsm4(qf[u][ks], addr);
                }
        }

        const int buf = kt & 1;
        const uint32_t kb = smKV + buf * 36864;
        const uint32_t vb = kb + 18432;

        uint4 mw[4];
#pragma unroll
        for (int rr = 0; rr < 4; rr++) mw[rr] = bmp[rr][kt];

        // ---- four 32-column slices, processed sequentially ----
#pragma unroll
        for (int nq = 0; nq < 4; nq++) {
            // S = Q K^T (log2 domain, fp32 acc) for cols [32*nq, 32*nq+32)
            float s[2][4][4];
#pragma unroll
            for (int u = 0; u < 2; u++)
#pragma unroll
                for (int j = 0; j < 4; j++)
#pragma unroll
                    for (int r = 0; r < 4; r++) s[u][j][r] = 0.0f;
#pragma unroll
            for (int j2p = 0; j2p < 2; j2p++) {
                const int j2 = nq * 4 + 2 * j2p;     // 8-col group (0..15)
#pragma unroll
                for (int ks = 0; ks < 4; ks++) {
                    uint32_t kr[4];
                    uint32_t addr = kb +
                        (8 * j2 + (lane & 7) + ((lane >> 4) << 3)) * 144 +
                        (ks * 16 + ((lane >> 3) & 1) * 8) * 2;
                    ldsm4(kr, addr);
                    mma16816(s[0][2 * j2p],     qf[0][ks], kr[0], kr[1]);
                    mma16816(s[0][2 * j2p + 1], qf[0][ks], kr[2], kr[3]);
                    mma16816(s[1][2 * j2p],     qf[1][ks], kr[0], kr[1]);
                    mma16816(s[1][2 * j2p + 1], qf[1][ks], kr[2], kr[3]);
                }
            }

            // p = maskbit ? 2^s : 0   (no bias; f16x2 MUFU; bitwise mask)
            uint32_t ph[2][4][2];
#pragma unroll
            for (int u = 0; u < 2; u++) {
                const uint32_t wlo = nq == 0 ? mw[2 * u].x : nq == 1 ? mw[2 * u].y
                                   : nq == 2 ? mw[2 * u].z : mw[2 * u].w;
                const uint32_t whi = nq == 0 ? mw[2 * u + 1].x : nq == 1 ? mw[2 * u + 1].y
                                   : nq == 2 ? mw[2 * u + 1].z : mw[2 * u + 1].w;
#pragma unroll
                for (int j = 0; j < 4; j++) {
                    const int sh = 2 * qq + 8 * j;
                    uint32_t e01 = ex2h2(pack_h2(s[u][j][0], s[u][j][1]));
                    uint32_t e23 = ex2h2(pack_h2(s[u][j][2], s[u][j][3]));
                    uint32_t m01 = (((wlo >> sh) & 1u) ? 0x0000FFFFu : 0u) |
                                   (((wlo >> sh) & 2u) ? 0xFFFF0000u : 0u);
                    uint32_t m23 = (((whi >> sh) & 1u) ? 0x0000FFFFu : 0u) |
                                   (((whi >> sh) & 2u) ? 0xFFFF0000u : 0u);
                    ph[u][j][0] = e01 & m01;
                    ph[u][j][1] = e23 & m23;
                }
            }

            // O += P V (+ ones-column -> l) for V rows [32*nq, 32*nq+32)
#pragma unroll
            for (int tl = 0; tl < 2; tl++) {
                const int t = 2 * nq + tl;           // 16-row V group (0..7)
#pragma unroll
                for (int j2 = 0; j2 < 8; j2 += 2) {
                    uint32_t vr[4];
                    uint32_t addr = vb +
                        (16 * t + (lane & 7) + ((lane >> 3) & 1) * 8) * 144 +
                        (8 * j2 + (lane >> 4) * 8) * 2;
                    ldsm4t(vr, addr);
#pragma unroll
                    for (int u = 0; u < 2; u++) {
                        uint32_t a[4] = { ph[u][2 * tl][0], ph[u][2 * tl][1],
                                          ph[u][2 * tl + 1][0], ph[u][2 * tl + 1][1] };
                        mma16816(o[u][j2],     a, vr[0], vr[1]);
                        mma16816(o[u][j2 + 1], a, vr[2], vr[3]);
                    }
                }
                // ones column (cols 64-71; only col 64 meaningful)
                uint32_t vo[2];
                ldsm2t(vo, vb + (16 * t + (lane & 15)) * 144 + 128);
#pragma unroll
                for (int u = 0; u < 2; u++) {
                    uint32_t a[4] = { ph[u][2 * tl][0], ph[u][2 * tl][1],
                                      ph[u][2 * tl + 1][0], ph[u][2 * tl + 1][1] };
                    mma16816(ol[u], a, vo[0], vo[1]);
                }
            }
        }

        __syncthreads();     // all warps done reading buf before refill
        if (kt + 2 < 32) { loadKV(kt + 2, buf); }
        cp_commit();
    }

    // ---- epilogue: l lives in qq==0 lanes (col 64 of ones group) ----
#pragma unroll
    for (int u = 0; u < 2; u++) {
        int src = lane & 28;                       // lane with qq==0, same g
        float l0 = __shfl_sync(0xffffffffu, ol[u][0], src);
        float l1 = __shfl_sync(0xffffffffu, ol[u][2], src);
        float il0 = 1.0f / l0;
        float il1 = 1.0f / l1;
        size_t rbase = ((size_t)(b * S_) + q0 + m0 + u * 16 + g) * D_ + h * 64;
#pragma unroll
        for (int j = 0; j < 8; j++) {
            int col = 8 * j + 2 * qq;
            *(uint32_t*)(Y + rbase + col) =
                pack_h2(o[u][j][0] * il0, o[u][j][1] * il0);
            *(uint32_t*)(Y + rbase + 8 * (size_t)D_ + col) =
                pack_h2(o[u][j][2] * il1, o[u][j][3] * il1);
        }
    }
}

// ---------------------------------------------------------------------------
extern "C" void kernel_launch(void* const* d_in, const int* in_sizes, int n_in,
                              void* d_out, int out_size)
{
    const float* q    = (const float*)d_in[0];
    const float* k    = (const float*)d_in[1];
    const float* v    = (const float*)d_in[2];
    const int*   mask = (const int*)d_in[3];
    const float* w_q  = (const float*)d_in[4];
    const float* w_k  = (const float*)d_in[5];
    const float* w_v  = (const float*)d_in[6];
    const float* w_o  = (const float*)d_in[7];
    float* out = (float*)d_out;

    __half *Qh, *Kh, *Vh, *Yb;
    uint32_t* Mb;
    cudaGetSymbolAddress((void**)&Qh, g_Q);
    cudaGetSymbolAddress((void**)&Kh, g_K);
    cudaGetSymbolAddress((void**)&Vh, g_V);
    cudaGetSymbolAddress((void**)&Yb, g_Y);
    cudaGetSymbolAddress((void**)&Mb, g_M);

    static int init = 0;
    if (!init) {
        cudaFuncSetAttribute(flash16, cudaFuncAttributeMaxDynamicSharedMemorySize,
                             FL_SMEM);
        init = 1;
    }

    maskpack<<<1024, 256>>>(mask, Mb);

    // fused QKV projections; Q scale = (1/sqrt(dk))*log2(e) -> log2-domain scores
    dim3 pgrid3(4, 64, 3);
    proj9<float, true, __half><<<pgrid3, 256>>>(q, k, v, w_q, w_k, w_v,
                                                Qh, Kh, Vh, 0.125f * 1.44269504f);

    dim3 fgrid(16, 32);   // x = b*h, y = q-tile of 128
    flash16<<<fgrid, 128, FL_SMEM>>>(Qh, Kh, Vh, Mb, Yb);

    dim3 pgrid(4, 64, 1);
    proj9<__half, false, float><<<pgrid, 256>>>(Yb, Yb, Yb, w_o, w_o, w_o,
                                                out, out, out, 1.0f);
}